// round 5
// baseline (speedup 1.0000x reference)
#include <cuda_runtime.h>
#include <math.h>

#define B_    16
#define LQ_   2048
#define EMB1_ 1024
#define EMB2_ 768
#define HDIM_ 1024
#define NHEAD_ 16
#define DH_   64

// Scratch (no allocation allowed -> __device__ globals)
__device__ float g_KV[2 * B_ * HDIM_];        // K at offset 0, V at offset B_*HDIM_ ; layout [b][i]
__device__ float g_Wqk[B_ * NHEAD_ * EMB1_];  // [b][h][e]
__device__ float g_c[B_ * NHEAD_];            // [b][h]

// Packed fp32x2 FMA (Blackwell-only; ptxas never auto-fuses this)
__device__ __forceinline__ void ffma2(unsigned long long& d,
                                      unsigned long long a,
                                      unsigned long long b) {
    asm("fma.rn.f32x2 %0, %1, %2, %0;" : "+l"(d) : "l"(a), "l"(b));
}
__device__ __forceinline__ float unpack_sum(unsigned long long v) {
    float lo, hi;
    asm("mov.b64 {%0, %1}, %2;" : "=f"(lo), "=f"(hi) : "l"(v));
    return lo + hi;
}

// Split-merge butterfly step: after the full tree, lanes whose (lane&off)==0
// carry a's reduction branch, (lane&off)!=0 carry b's.
__device__ __forceinline__ float merge2(float a, float b, int off, int lane) {
    bool hi = (lane & off) != 0;
    float keep = hi ? b : a;
    float send = hi ? a : b;
    return keep + __shfl_xor_sync(0xffffffffu, send, off);
}

// ---------------------------------------------------------------------------
// Kernel A: K[b,i] = emb2[b,:]·Wk[i,:] + bk[i]; V likewise.
// grid 128 blocks x 256 thr; block handles 8 rows i (one per warp), both K and V.
// ---------------------------------------------------------------------------
__global__ __launch_bounds__(256) void kv_kernel(
    const float* __restrict__ emb2,
    const float* __restrict__ Wk, const float* __restrict__ bk,
    const float* __restrict__ Wv, const float* __restrict__ bv)
{
    __shared__ float4 e2s[B_ * EMB2_ / 4];  // 3072 float4 = 48 KB
    const float4* in4 = (const float4*)emb2;
    for (int i = threadIdx.x; i < B_ * EMB2_ / 4; i += 256) e2s[i] = in4[i];
    __syncthreads();

    const int w = threadIdx.x >> 5;
    const int l = threadIdx.x & 31;
    const int row = blockIdx.x * 8 + w;  // 0..1023

    #pragma unroll
    for (int kv = 0; kv < 2; ++kv) {
        const float* W    = kv ? Wv : Wk;
        const float* bias = kv ? bv : bk;
        const float4* Wr = (const float4*)(W + (size_t)row * EMB2_);
        float acc[16];
        #pragma unroll
        for (int b = 0; b < 16; ++b) acc[b] = 0.f;
        #pragma unroll
        for (int j = 0; j < 6; ++j) {           // 768/4 = 192 float4, 32-lane stride
            float4 wv4 = __ldg(Wr + l + 32 * j);
            #pragma unroll
            for (int b = 0; b < 16; ++b) {
                float4 e = e2s[b * 192 + l + 32 * j];
                acc[b] += wv4.x * e.x + wv4.y * e.y + wv4.z * e.z + wv4.w * e.w;
            }
        }
        #pragma unroll
        for (int off = 16; off; off >>= 1) {
            #pragma unroll
            for (int b = 0; b < 16; ++b)
                acc[b] += __shfl_xor_sync(0xffffffffu, acc[b], off);
        }
        if (l < 16)
            g_KV[kv * B_ * HDIM_ + l * HDIM_ + row] = acc[l] + __ldg(bias + row);
    }
}

// ---------------------------------------------------------------------------
// Kernel B: Wqk[b,h,e] = sum_d Wq[h*64+d, e] * K[b, h*64+d]; c[b,h] = bq·K slice.
// grid (8 e-chunks of 128, 16 heads) x 128 thr.
// ---------------------------------------------------------------------------
__global__ __launch_bounds__(128) void wqk_kernel(
    const float* __restrict__ Wq, const float* __restrict__ bq)
{
    const int h  = blockIdx.y;      // 0..15
    const int ec = blockIdx.x;      // 0..7
    const int e0 = ec * 128;

    __shared__ float Wq_s[64 * 128];  // 32 KB: [d][e_local]
    __shared__ float K_s[16 * 64];    // 4 KB:  [b][d]
    __shared__ float bq_s[64];

    for (int i = threadIdx.x; i < 64 * 128 / 4; i += 128) {
        int d = i >> 5;   // 32 float4 per row
        int c = i & 31;
        ((float4*)Wq_s)[i] =
            __ldg((const float4*)(Wq + (size_t)(h * 64 + d) * EMB1_ + e0) + c);
    }
    for (int i = threadIdx.x; i < 16 * 64; i += 128) {
        int b = i >> 6, d = i & 63;
        K_s[i] = g_KV[b * HDIM_ + h * 64 + d];
    }
    if (threadIdx.x < 64) bq_s[threadIdx.x] = __ldg(bq + h * 64 + threadIdx.x);
    __syncthreads();

    float acc[16];
    #pragma unroll
    for (int b = 0; b < 16; ++b) acc[b] = 0.f;
    const int e = threadIdx.x;  // 0..127
    #pragma unroll 8
    for (int d = 0; d < 64; ++d) {
        float wq = Wq_s[d * 128 + e];
        #pragma unroll
        for (int b = 0; b < 16; ++b)
            acc[b] = fmaf(wq, K_s[b * 64 + d], acc[b]);
    }
    #pragma unroll
    for (int b = 0; b < 16; ++b)
        g_Wqk[(size_t)(b * NHEAD_ + h) * EMB1_ + e0 + e] = acc[b];

    if (ec == 0 && threadIdx.x < 16) {
        int b = threadIdx.x;
        float s = 0.f;
        #pragma unroll
        for (int d = 0; d < 64; ++d) s = fmaf(bq_s[d], K_s[b * 64 + d], s);
        g_c[b * NHEAD_ + h] = s;
    }
}

// ---------------------------------------------------------------------------
// Kernel C (main): out[b,q,h*64+d] = sigmoid(emb1[b,q,:]·Wqk[b,h,:] + c[b,h]) * V[b,h*64+d]
// grid (32 q-tiles of 64, 16 batches) x 256 thr.
// Each CTA stages Wqk[b] (64KB) + V[b] once, then processes TWO 32-row
// subtiles, amortizing the staging cost and halving Wqk L2 traffic.
// Inner loop: packed fma.rn.f32x2 with software-pipelined emb1 prefetch;
// sub=0's first prefetch issued BEFORE the staging barrier.
// Reduction: split-merge butterfly (16 SHFL/row instead of 80).
// ---------------------------------------------------------------------------
__global__ __launch_bounds__(256) void mha_main_kernel(
    const float* __restrict__ emb1, float* __restrict__ out)
{
    const int b      = blockIdx.y;
    const int qbase0 = blockIdx.x * 64;

    extern __shared__ float smem[];
    float* Wqk_s = smem;                 // 16384 floats
    float* V_s   = smem + 16 * 1024;     // 1024
    float* sig_s = V_s + 1024;           // 32*16 = 512
    float* c_s   = sig_s + 512;          // 16

    const int w = threadIdx.x >> 5;
    const int l = threadIdx.x & 31;

    // Each 16B vector = two packed f32x2 operands; no pack instructions needed.
    const ulonglong2* e1row[4];
    #pragma unroll
    for (int r = 0; r < 4; ++r)
        e1row[r] = (const ulonglong2*)(emb1 + (size_t)(b * LQ_ + qbase0 + w * 4 + r) * EMB1_);

    // Issue the first emb1 prefetch (sub=0) before staging: overlaps DRAM
    // latency with the 64KB Wqk smem fill.
    ulonglong2 e_cur[4], e_nxt[4];
    #pragma unroll
    for (int r = 0; r < 4; ++r) e_cur[r] = e1row[r][l];

    {
        const float4* src = (const float4*)(g_Wqk + (size_t)b * NHEAD_ * EMB1_);
        float4* dst = (float4*)Wqk_s;
        for (int i = threadIdx.x; i < 4096; i += 256) dst[i] = src[i];
        ((float4*)V_s)[threadIdx.x] =
            ((const float4*)(g_KV + B_ * HDIM_ + (size_t)b * HDIM_))[threadIdx.x];
        if (threadIdx.x < 16) c_s[threadIdx.x] = g_c[b * NHEAD_ + threadIdx.x];
    }
    __syncthreads();

    const ulonglong2* Wqk2 = (const ulonglong2*)Wqk_s;
    const int head_out = threadIdx.x >> 4;            // output-phase head
    const float4 v4 = ((const float4*)V_s)[threadIdx.x];

    #pragma unroll 1
    for (int sub = 0; sub < 2; ++sub) {
        const int qbase = qbase0 + sub * 32;
        if (sub > 0) {
            // advance row pointers to the second subtile and load first chunk
            #pragma unroll
            for (int r = 0; r < 4; ++r) {
                e1row[r] += 32 * (EMB1_ / 4) / 4 * 0 + (size_t)32 * EMB1_ / 4; // +32 rows
                e_cur[r] = e1row[r][l];
            }
        }

        unsigned long long acc[4][16];
        #pragma unroll
        for (int r = 0; r < 4; ++r)
            #pragma unroll
            for (int h = 0; h < 16; ++h) acc[r][h] = 0ull;

        #pragma unroll
        for (int j = 0; j < 8; ++j) {
            const int idx = l + 32 * j;
            if (j < 7) {
                #pragma unroll
                for (int r = 0; r < 4; ++r) e_nxt[r] = e1row[r][idx + 32];
            }
            #pragma unroll
            for (int h = 0; h < 16; ++h) {
                ulonglong2 wp = Wqk2[h * 256 + idx];
                #pragma unroll
                for (int r = 0; r < 4; ++r) {
                    ffma2(acc[r][h], wp.x, e_cur[r].x);
                    ffma2(acc[r][h], wp.y, e_cur[r].y);
                }
            }
            #pragma unroll
            for (int r = 0; r < 4; ++r) e_cur[r] = e_nxt[r];
        }

        // Per-row split-merge reduction: 16 SHFL per row instead of 80.
        #pragma unroll
        for (int r = 0; r < 4; ++r) {
            float part[16];
            #pragma unroll
            for (int h = 0; h < 16; ++h) part[h] = unpack_sum(acc[r][h]);

            float m1[8];
            #pragma unroll
            for (int h = 0; h < 8; ++h) m1[h] = merge2(part[h], part[h + 8], 16, l);
            float m2[4];
            #pragma unroll
            for (int h = 0; h < 4; ++h) m2[h] = merge2(m1[h], m1[h + 4], 8, l);
            float m3[2];
            #pragma unroll
            for (int h = 0; h < 2; ++h) m3[h] = merge2(m2[h], m2[h + 2], 4, l);
            float m4 = merge2(m3[0], m3[1], 2, l);
            m4 += __shfl_xor_sync(0xffffffffu, m4, 1);

            // even lane l holds head: bit4->+8, bit3->+4, bit2->+2, bit1->+1
            const int head = ((l >> 4) & 1) * 8 + ((l >> 3) & 1) * 4
                           + ((l >> 2) & 1) * 2 + ((l >> 1) & 1);
            if (!(l & 1)) {
                float att = m4 + c_s[head];
                sig_s[(w * 4 + r) * 16 + head] = 1.f / (1.f + __expf(-att));
            }
        }
        __syncthreads();

        // Output: thread tid owns float4 column tid (cols 4*tid..4*tid+3)
        float4* outp = (float4*)out + (size_t)(b * LQ_ + qbase) * 256 + threadIdx.x;
        #pragma unroll 4
        for (int r = 0; r < 32; ++r) {
            float g = sig_s[r * 16 + head_out];
            float4 o = make_float4(g * v4.x, g * v4.y, g * v4.z, g * v4.w);
            outp[(size_t)r * 256] = o;
        }
        __syncthreads();   // protect sig_s before next subtile rewrites it
    }
}

// ---------------------------------------------------------------------------
extern "C" void kernel_launch(void* const* d_in, const int* in_sizes, int n_in,
                              void* d_out, int out_size)
{
    (void)in_sizes; (void)n_in; (void)out_size;
    const float* emb1 = (const float*)d_in[0];
    const float* emb2 = (const float*)d_in[1];
    const float* Wq   = (const float*)d_in[2];
    const float* bq   = (const float*)d_in[3];
    const float* Wk   = (const float*)d_in[4];
    const float* bk   = (const float*)d_in[5];
    const float* Wv   = (const float*)d_in[6];
    const float* bv   = (const float*)d_in[7];
    float* out = (float*)d_out;

    kv_kernel<<<128, 256>>>(emb2, Wk, bk, Wv, bv);
    wqk_kernel<<<dim3(8, 16), 128>>>(Wq, bq);

    const size_t smemC = (16 * 1024 + 1024 + 512 + 16) * sizeof(float);  // 70272 B
    cudaFuncSetAttribute(mha_main_kernel,
                         cudaFuncAttributeMaxDynamicSharedMemorySize, (int)smemC);
    mha_main_kernel<<<dim3(32, 16), 256, smemC>>>(emb1, out);
}